// round 10
// baseline (speedup 1.0000x reference)
#include <cuda_runtime.h>
#include <cuda_fp16.h>
#include <cstdint>

// Problem constants
#define TOKENS 32768          // B*S = 16*2048
#define FDIM   1024
#define NQKV   3072
#define NHEAD  16
#define DHEAD  64

// ---------------------------------------------------------------------------
// Scratch (device globals; no allocations allowed)
// ---------------------------------------------------------------------------
__device__ __align__(16) half  g_Wqkv[(size_t)NQKV * FDIM];     // [N=3072, K=1024] transposed
__device__ __align__(16) half  g_Wo16[(size_t)FDIM * FDIM];     // [N=1024, K=1024] transposed
__device__ float               g_bqkv[NQKV];                    // packed biases
__device__ __align__(16) half  g_QKV [(size_t)TOKENS * NQKV];   // q,k,v per token
__device__ __align__(16) half  g_Attn[(size_t)TOKENS * FDIM];   // attention output

// ---------------------------------------------------------------------------
// PTX helpers
// ---------------------------------------------------------------------------
__device__ __forceinline__ void cp_async16(void* dst, const void* src){
    unsigned s = (unsigned)__cvta_generic_to_shared(dst);
    asm volatile("cp.async.cg.shared.global [%0], [%1], 16;\n" :: "r"(s), "l"(src));
}
__device__ __forceinline__ void cp_commit(){ asm volatile("cp.async.commit_group;\n"); }
template<int N>
__device__ __forceinline__ void cp_wait(){ asm volatile("cp.async.wait_group %0;\n" :: "n"(N)); }

__device__ __forceinline__ void ldsm_x4(uint32_t* r, uint32_t addr){
    asm volatile("ldmatrix.sync.aligned.m8n8.x4.shared.b16 {%0,%1,%2,%3}, [%4];\n"
        : "=r"(r[0]), "=r"(r[1]), "=r"(r[2]), "=r"(r[3]) : "r"(addr));
}
__device__ __forceinline__ void ldsm_x4_t(uint32_t* r, uint32_t addr){
    asm volatile("ldmatrix.sync.aligned.m8n8.x4.trans.shared.b16 {%0,%1,%2,%3}, [%4];\n"
        : "=r"(r[0]), "=r"(r[1]), "=r"(r[2]), "=r"(r[3]) : "r"(addr));
}
__device__ __forceinline__ void mma16816(float* c, const uint32_t* a, const uint32_t* b){
    asm volatile("mma.sync.aligned.m16n8k16.row.col.f32.f16.f16.f32 "
        "{%0,%1,%2,%3}, {%4,%5,%6,%7}, {%8,%9}, {%0,%1,%2,%3};\n"
        : "+f"(c[0]), "+f"(c[1]), "+f"(c[2]), "+f"(c[3])
        : "r"(a[0]), "r"(a[1]), "r"(a[2]), "r"(a[3]), "r"(b[0]), "r"(b[1]));
}
__device__ __forceinline__ uint32_t h2_to_u32(half2 h){
    uint32_t u;
    memcpy(&u, &h, 4);
    return u;
}
__device__ __forceinline__ uint32_t cluster_rank(){
    uint32_t r;
    asm("mov.u32 %0, %%cluster_ctarank;" : "=r"(r));
    return r;
}

// ---------------------------------------------------------------------------
// Pack biases
// ---------------------------------------------------------------------------
__global__ void __launch_bounds__(256) packb_kernel(
    const float* __restrict__ bq, const float* __restrict__ bk, const float* __restrict__ bv)
{
    int i = blockIdx.x * blockDim.x + threadIdx.x;
    if (i < NQKV)
        g_bqkv[i] = (i < 1024) ? bq[i] : (i < 2048) ? bk[i - 1024] : bv[i - 2048];
}

// ---------------------------------------------------------------------------
// Tiled transpose: W[k][n] fp32 -> Wt[n][k] fp16.  z: 0..2 -> Wqkv rows, 3 -> Wo
// ---------------------------------------------------------------------------
__global__ void __launch_bounds__(256) transw_kernel(
    const float* __restrict__ Wq, const float* __restrict__ Wk,
    const float* __restrict__ Wv, const float* __restrict__ Wo)
{
    __shared__ float t[32][33];
    const int z = blockIdx.z;
    const float* src = (z == 0) ? Wq : (z == 1) ? Wk : (z == 2) ? Wv : Wo;
    const int k0 = blockIdx.y * 32, n0 = blockIdx.x * 32;
    const int tx = threadIdx.x, ty = threadIdx.y;   // 32 x 8
    #pragma unroll
    for (int i = 0; i < 4; ++i)
        t[ty + i * 8][tx] = src[(size_t)(k0 + ty + i * 8) * FDIM + n0 + tx];
    __syncthreads();
    half* dst = (z < 3) ? (g_Wqkv + (size_t)z * FDIM * FDIM) : g_Wo16;
    #pragma unroll
    for (int i = 0; i < 4; ++i)
        dst[(size_t)(n0 + ty + i * 8) * FDIM + k0 + tx] = __float2half_rn(t[tx][ty + i * 8]);
}

// ---------------------------------------------------------------------------
// GEMM1 (HMMA): QKV[M,3072] = x[M,1024](fp32, inline-converted) * Wqkv^T + bqkv
//   CTA tile 128x256, 8 warps (2x4), warp tile 64x64, BK=64, 4-stage ring.
//   A path: early LDG.128 (pre-barrier) -> cvt+STS (post-MMA).
// ---------------------------------------------------------------------------
#define BM 128
#define BN 256
#define BK 64
#define SROW 72
#define A_ST_BYTES (BM * SROW * 2)
#define B_ST_BYTES (BN * SROW * 2)
#define STAGE_BYTES (A_ST_BYTES + B_ST_BYTES)
#define NSTAGES 4
#define NKBLK (FDIM / BK)
#define GEMM_DSMEM (NSTAGES * STAGE_BYTES)

__global__ void __launch_bounds__(256, 1) gemm1_kernel(const float* __restrict__ xf)
{
    extern __shared__ __align__(16) half sm[];

    const int tid  = threadIdx.x;
    const int lane = tid & 31;
    const int wid  = tid >> 5;
    const int wm   = wid & 1;
    const int wn   = wid >> 1;
    const int m0 = blockIdx.y * BM;
    const int n0 = blockIdx.x * BN;

    const float* Xbase = xf + (size_t)m0 * FDIM;
    const half*  Bbase = g_Wqkv + (size_t)n0 * FDIM;

    float acc[4][8][4];
    #pragma unroll
    for (int mi = 0; mi < 4; ++mi)
        #pragma unroll
        for (int ni = 0; ni < 8; ++ni)
            #pragma unroll
            for (int t = 0; t < 4; ++t) acc[mi][ni][t] = 0.f;

    auto loadB = [&](int s){
        const int buf = s & (NSTAGES - 1);
        half* bs = sm + (size_t)buf * (STAGE_BYTES / 2) + (A_ST_BYTES / 2);
        const half* Bsrc = Bbase + s * BK;
        #pragma unroll
        for (int i = 0; i < 8; ++i){
            int idx = tid + i * 256;
            int r = idx >> 3, c = idx & 7;
            cp_async16(bs + r * SROW + c * 8, Bsrc + (size_t)r * FDIM + c * 8);
        }
        cp_commit();
    };
    auto ldgA = [&](int s, float4* ar){
        const float* Asrc = Xbase + s * BK;
        #pragma unroll
        for (int i = 0; i < 4; ++i){
            int idx = tid + i * 256;
            int r = idx >> 3, c = idx & 7;
            const float4* p = (const float4*)(Asrc + (size_t)r * FDIM + c * 8);
            ar[2 * i]     = p[0];
            ar[2 * i + 1] = p[1];
        }
    };
    auto stsA = [&](int s, const float4* ar){
        const int buf = s & (NSTAGES - 1);
        half* as = sm + (size_t)buf * (STAGE_BYTES / 2);
        #pragma unroll
        for (int i = 0; i < 4; ++i){
            int idx = tid + i * 256;
            int r = idx >> 3, c = idx & 7;
            float4 a0 = ar[2 * i], a1 = ar[2 * i + 1];
            uint4 packed;
            packed.x = h2_to_u32(__floats2half2_rn(a0.x, a0.y));
            packed.y = h2_to_u32(__floats2half2_rn(a0.z, a0.w));
            packed.z = h2_to_u32(__floats2half2_rn(a1.x, a1.y));
            packed.w = h2_to_u32(__floats2half2_rn(a1.z, a1.w));
            *(uint4*)(as + r * SROW + c * 8) = packed;
        }
    };

    #pragma unroll
    for (int s = 0; s < 3; ++s){
        float4 ar[8];
        ldgA(s, ar);
        stsA(s, ar);
        loadB(s);
    }

    const int a_row = wm * 64 + (lane & 15);
    const int a_colb = (lane >> 4) << 3;
    const int b_row = wn * 64 + (lane & 7) + ((lane >> 4) << 3);
    const int b_colb = ((lane >> 3) & 1) << 3;

    for (int s = 0; s < NKBLK; ++s){
        const bool pre = (s + 3 < NKBLK);
        float4 ar[8];
        if (pre) ldgA(s + 3, ar);

        const int rem = (NKBLK - 1) - s;
        if (rem >= 2)      cp_wait<2>();
        else if (rem == 1) cp_wait<1>();
        else               cp_wait<0>();
        __syncthreads();

        if (pre) loadB(s + 3);

        const int buf = s & (NSTAGES - 1);
        const half* as = sm + (size_t)buf * (STAGE_BYTES / 2);
        const half* bs = as + (A_ST_BYTES / 2);
        const uint32_t aB = (uint32_t)__cvta_generic_to_shared(as);
        const uint32_t bB = (uint32_t)__cvta_generic_to_shared(bs);

        #pragma unroll
        for (int kk = 0; kk < 4; ++kk){
            const int k16 = kk * 16;
            uint32_t a[4][4], b[8][2];
            #pragma unroll
            for (int mi = 0; mi < 4; ++mi){
                uint32_t addr = aB + (uint32_t)(((a_row + mi * 16) * SROW + k16 + a_colb) * 2);
                ldsm_x4(&a[mi][0], addr);
            }
            #pragma unroll
            for (int nb = 0; nb < 4; ++nb){
                uint32_t addr = bB + (uint32_t)(((b_row + nb * 16) * SROW + k16 + b_colb) * 2);
                uint32_t r[4];
                ldsm_x4(r, addr);
                b[nb * 2][0] = r[0];     b[nb * 2][1] = r[1];
                b[nb * 2 + 1][0] = r[2]; b[nb * 2 + 1][1] = r[3];
            }
            #pragma unroll
            for (int mi = 0; mi < 4; ++mi)
                #pragma unroll
                for (int ni = 0; ni < 8; ++ni)
                    mma16816(acc[mi][ni], a[mi], b[ni]);
        }

        if (pre) stsA(s + 3, ar);
    }

    #pragma unroll
    for (int mi = 0; mi < 4; ++mi){
        #pragma unroll
        for (int ni = 0; ni < 8; ++ni){
            int r = m0 + wm * 64 + mi * 16 + (lane >> 2);
            int c = n0 + wn * 64 + ni * 8 + ((lane & 3) << 1);
            float b0 = g_bqkv[c], b1 = g_bqkv[c + 1];
            float v0 = acc[mi][ni][0] + b0, v1 = acc[mi][ni][1] + b1;
            float v2 = acc[mi][ni][2] + b0, v3 = acc[mi][ni][3] + b1;
            *(half2*)(g_QKV + (size_t)r * NQKV + c)       = __floats2half2_rn(v0, v1);
            *(half2*)(g_QKV + (size_t)(r + 8) * NQKV + c) = __floats2half2_rn(v2, v3);
        }
    }
}

// ---------------------------------------------------------------------------
// Tensor-core per-token attention. 1 warp per token, 8 tokens per block.
// ---------------------------------------------------------------------------
#define ATOK_ROWS 48
#define ATOK_H (ATOK_ROWS * 72)            // 3456 halfs per token
#define ATTN_DSMEM (8 * ATOK_H * 2)        // 55296 bytes

__global__ void __launch_bounds__(256) attn_mma_kernel(){
    extern __shared__ __align__(16) half sm_a[];
    const int tid = threadIdx.x, lane = tid & 31, w = tid >> 5;
    const size_t tok0 = (size_t)blockIdx.x * 8;

    {
        const half* src = g_QKV + tok0 * NQKV;
        #pragma unroll
        for (int i = 0; i < 12; ++i){
            int idx = tid + i * 256;
            int tok = idx / 384, j = idx - tok * 384;
            int row = j >> 3, c = j & 7;
            cp_async16(sm_a + tok * ATOK_H + row * 72 + c * 8,
                       src + (size_t)tok * NQKV + j * 8);
        }
        cp_commit();
        cp_wait<0>();
    }
    __syncthreads();

    half* base = sm_a + w * ATOK_H;
    const uint32_t sb = (uint32_t)__cvta_generic_to_shared(base);

    float e0[4] = {0,0,0,0}, e1[4] = {0,0,0,0};
    {
        const int q_row  = lane & 15;
        const int q_colb = (lane >> 4) << 3;
        const int k_row  = 16 + (lane & 7) + ((lane >> 4) << 3);
        const int k_colb = ((lane >> 3) & 1) << 3;
        #pragma unroll
        for (int kc = 0; kc < 4; ++kc){
            const int k16 = kc * 16;
            uint32_t qa[4], kr[4];
            ldsm_x4(qa, sb + (uint32_t)((q_row * 72 + k16 + q_colb) * 2));
            ldsm_x4(kr, sb + (uint32_t)((k_row * 72 + k16 + k_colb) * 2));
            mma16816(e0, qa, &kr[0]);
            mma16816(e1, qa, &kr[2]);
        }
    }

    {
        const float sc = 0.125f;
        e0[0]*=sc; e0[1]*=sc; e0[2]*=sc; e0[3]*=sc;
        e1[0]*=sc; e1[1]*=sc; e1[2]*=sc; e1[3]*=sc;
        float mA = fmaxf(fmaxf(e0[0], e0[1]), fmaxf(e1[0], e1[1]));
        float mB = fmaxf(fmaxf(e0[2], e0[3]), fmaxf(e1[2], e1[3]));
        mA = fmaxf(mA, __shfl_xor_sync(0xffffffffu, mA, 1));
        mA = fmaxf(mA, __shfl_xor_sync(0xffffffffu, mA, 2));
        mB = fmaxf(mB, __shfl_xor_sync(0xffffffffu, mB, 1));
        mB = fmaxf(mB, __shfl_xor_sync(0xffffffffu, mB, 2));
        e0[0] = __expf(e0[0] - mA); e0[1] = __expf(e0[1] - mA);
        e1[0] = __expf(e1[0] - mA); e1[1] = __expf(e1[1] - mA);
        e0[2] = __expf(e0[2] - mB); e0[3] = __expf(e0[3] - mB);
        e1[2] = __expf(e1[2] - mB); e1[3] = __expf(e1[3] - mB);
        float sA = e0[0] + e0[1] + e1[0] + e1[1];
        float sB = e0[2] + e0[3] + e1[2] + e1[3];
        sA += __shfl_xor_sync(0xffffffffu, sA, 1);
        sA += __shfl_xor_sync(0xffffffffu, sA, 2);
        sB += __shfl_xor_sync(0xffffffffu, sB, 1);
        sB += __shfl_xor_sync(0xffffffffu, sB, 2);
        float iA = 1.f / sA, iB = 1.f / sB;
        e0[0]*=iA; e0[1]*=iA; e1[0]*=iA; e1[1]*=iA;
        e0[2]*=iB; e0[3]*=iB; e1[2]*=iB; e1[3]*=iB;
    }

    uint32_t pa[4];
    pa[0] = h2_to_u32(__floats2half2_rn(e0[0], e0[1]));
    pa[1] = h2_to_u32(__floats2half2_rn(e0[2], e0[3]));
    pa[2] = h2_to_u32(__floats2half2_rn(e1[0], e1[1]));
    pa[3] = h2_to_u32(__floats2half2_rn(e1[2], e1[3]));

    float o[8][4];
    #pragma unroll
    for (int nt = 0; nt < 8; ++nt){ o[nt][0]=0; o[nt][1]=0; o[nt][2]=0; o[nt][3]=0; }
    {
        const int v_row = 32 + (lane & 15);
        #pragma unroll
        for (int i = 0; i < 4; ++i){
            const int db = i * 16;
            uint32_t vr[4];
            ldsm_x4_t(vr, sb + (uint32_t)((v_row * 72 + db + ((lane >> 4) << 3)) * 2));
            mma16816(o[i * 2],     pa, &vr[0]);
            mma16816(o[i * 2 + 1], pa, &vr[2]);
        }
    }

    {
        const int r = lane >> 2;
        const int c2 = (lane & 3) << 1;
        #pragma unroll
        for (int nt = 0; nt < 8; ++nt){
            *(half2*)(base + r * 72 + nt * 8 + c2)       = __floats2half2_rn(o[nt][0], o[nt][1]);
            *(half2*)(base + (r + 8) * 72 + nt * 8 + c2) = __floats2half2_rn(o[nt][2], o[nt][3]);
        }
    }
    __syncthreads();

    {
        float4* gout = (float4*)(g_Attn + tok0 * FDIM);
        #pragma unroll
        for (int i = 0; i < 4; ++i){
            int idx = tid + i * 256;
            int tok = idx >> 7, j = idx & 127;
            int row = j >> 3, c = j & 7;
            gout[(size_t)tok * 128 + j] = *(const float4*)(sm_a + tok * ATOK_H + row * 72 + c * 8);
        }
    }
}

// ---------------------------------------------------------------------------
// GEMM2 + bias + LayerNorm fused, cluster(2):
//   out[M,1024] = LN(Attn @ Wo^T + bo)
//   CTA tile 64x512, 8 warps (wn 0..7), warp tile 64x64, BK=32, 4-stage ring.
//   The 2 CTAs of a cluster cover cols 0-511 / 512-1023 of the same 64 rows;
//   per-row partial sum/sumsq exchanged via DSMEM around a cluster barrier.
// ---------------------------------------------------------------------------
#define BM2 64
#define BN2 512
#define BK2 32
#define SROW2 40
#define A2_H (BM2 * SROW2)                 // 2560 halfs
#define B2_H (BN2 * SROW2)                 // 20480 halfs
#define STAGE2_H (A2_H + B2_H)             // 23040 halfs
#define NK2 (FDIM / BK2)                   // 32
#define G2_DSMEM (NSTAGES * STAGE2_H * 2)  // 184320 bytes

__global__ void __launch_bounds__(256, 1) __cluster_dims__(2, 1, 1)
gemm2_ln_kernel(const float* __restrict__ bo, const float* __restrict__ gamma,
                const float* __restrict__ beta, float* __restrict__ out)
{
    extern __shared__ __align__(16) half sm2[];
    __shared__ float s_ps[BM2][8], s_pq[BM2][8];
    __shared__ __align__(8) float s_cta[BM2][2];
    __shared__ float s_stats[BM2][2];

    const int tid  = threadIdx.x;
    const int lane = tid & 31;
    const int wn   = tid >> 5;          // 0..7 -> 64-col slice
    const int m0 = blockIdx.y * BM2;
    const int n0 = blockIdx.x * BN2;

    const half* Abase = g_Attn + (size_t)m0 * FDIM;
    const half* Bbase = g_Wo16 + (size_t)n0 * FDIM;

    float acc[4][8][4];
    #pragma unroll
    for (int mi = 0; mi < 4; ++mi)
        #pragma unroll
        for (int ni = 0; ni < 8; ++ni)
            #pragma unroll
            for (int t = 0; t < 4; ++t) acc[mi][ni][t] = 0.f;

    auto load_stage = [&](int s){
        const int buf = s & (NSTAGES - 1);
        half* as = sm2 + (size_t)buf * STAGE2_H;
        half* bs = as + A2_H;
        const half* Asrc = Abase + s * BK2;
        const half* Bsrc = Bbase + s * BK2;
        {   // A: 64 rows x 4 chunks = 256 tasks
            int r = tid >> 2, c = tid & 3;
            cp_async16(as + r * SROW2 + c * 8, Asrc + (size_t)r * FDIM + c * 8);
        }
        #pragma unroll
        for (int i = 0; i < 8; ++i){   // B: 512 rows x 4 chunks = 2048 tasks
            int idx = tid + i * 256;
            int r = idx >> 2, c = idx & 3;
            cp_async16(bs + r * SROW2 + c * 8, Bsrc + (size_t)r * FDIM + c * 8);
        }
        cp_commit();
    };

    load_stage(0); load_stage(1); load_stage(2);

    const int a_row = lane & 15;
    const int a_colb = (lane >> 4) << 3;
    const int b_row = wn * 64 + (lane & 7) + ((lane >> 4) << 3);
    const int b_colb = ((lane >> 3) & 1) << 3;

    for (int s = 0; s < NK2; ++s){
        const int rem = (NK2 - 1) - s;
        if (rem >= 2)      cp_wait<2>();
        else if (rem == 1) cp_wait<1>();
        else               cp_wait<0>();
        __syncthreads();

        if (s + 3 < NK2) load_stage(s + 3);

        const int buf = s & (NSTAGES - 1);
        const half* as = sm2 + (size_t)buf * STAGE2_H;
        const half* bs = as + A2_H;
        const uint32_t aB = (uint32_t)__cvta_generic_to_shared(as);
        const uint32_t bB = (uint32_t)__cvta_generic_to_shared(bs);

        #pragma unroll
        for (int kk = 0; kk < 2; ++kk){
            const int k16 = kk * 16;
            uint32_t a[4][4], b[8][2];
            #pragma unroll
            for (int mi = 0; mi < 4; ++mi){
                uint32_t addr = aB + (uint32_t)(((a_row + mi * 16) * SROW2 + k16 + a_colb) * 2);
                ldsm_x4(&a[mi][0], addr);
            }
            #pragma unroll
            for (int nb = 0; nb < 4; ++nb){
                uint32_t addr = bB + (uint32_t)(((b_row + nb * 16) * SROW2 + k16 + b_colb) * 2);
                uint32_t r[4];
                ldsm_x4(r, addr);
                b[nb * 2][0] = r[0];     b[nb * 2][1] = r[1];
                b[nb * 2 + 1][0] = r[2]; b[nb * 2 + 1][1] = r[3];
            }
            #pragma unroll
            for (int mi = 0; mi < 4; ++mi)
                #pragma unroll
                for (int ni = 0; ni < 8; ++ni)
                    mma16816(acc[mi][ni], a[mi], b[ni]);
        }
    }

    // ---- bias + per-thread partial sums over its 16 cols (8 rows each) ----
    const int r_base = lane >> 2;
    const int c_lane = (lane & 3) << 1;
    float ps[4][2] = {}, pq[4][2] = {};
    #pragma unroll
    for (int mi = 0; mi < 4; ++mi){
        #pragma unroll
        for (int ni = 0; ni < 8; ++ni){
            int c = n0 + wn * 64 + ni * 8 + c_lane;
            float b0 = bo[c], b1 = bo[c + 1];
            float v0 = acc[mi][ni][0] + b0, v1 = acc[mi][ni][1] + b1;
            float v2 = acc[mi][ni][2] + b0, v3 = acc[mi][ni][3] + b1;
            acc[mi][ni][0] = v0; acc[mi][ni][1] = v1;
            acc[mi][ni][2] = v2; acc[mi][ni][3] = v3;
            ps[mi][0] += v0 + v1;          pq[mi][0] += v0*v0 + v1*v1;
            ps[mi][1] += v2 + v3;          pq[mi][1] += v2*v2 + v3*v3;
        }
    }
    #pragma unroll
    for (int mi = 0; mi < 4; ++mi)
        #pragma unroll
        for (int hh = 0; hh < 2; ++hh){
            ps[mi][hh] += __shfl_xor_sync(0xffffffffu, ps[mi][hh], 1);
            ps[mi][hh] += __shfl_xor_sync(0xffffffffu, ps[mi][hh], 2);
            pq[mi][hh] += __shfl_xor_sync(0xffffffffu, pq[mi][hh], 1);
            pq[mi][hh] += __shfl_xor_sync(0xffffffffu, pq[mi][hh], 2);
        }
    if ((lane & 3) == 0){
        #pragma unroll
        for (int mi = 0; mi < 4; ++mi)
            #pragma unroll
            for (int hh = 0; hh < 2; ++hh){
                int row = mi * 16 + hh * 8 + r_base;
                s_ps[row][wn] = ps[mi][hh];
                s_pq[row][wn] = pq[mi][hh];
            }
    }
    __syncthreads();

    // ---- CTA-level per-row partials ----
    if (tid < BM2){
        float S = 0.f, Q = 0.f;
        #pragma unroll
        for (int k = 0; k < 8; ++k){ S += s_ps[tid][k]; Q += s_pq[tid][k]; }
        s_cta[tid][0] = S; s_cta[tid][1] = Q;
    }
    __syncthreads();

    // ---- cluster exchange: add peer CTA's per-row partials ----
    asm volatile("barrier.cluster.arrive.aligned;" ::: "memory");
    asm volatile("barrier.cluster.wait.aligned;"   ::: "memory");
    if (tid < BM2){
        const uint32_t peer = cluster_rank() ^ 1u;
        uint32_t laddr = (uint32_t)__cvta_generic_to_shared(&s_cta[tid][0]);
        uint32_t raddr;
        asm("mapa.shared::cluster.u32 %0, %1, %2;" : "=r"(raddr) : "r"(laddr), "r"(peer));
        float pS, pQ;
        asm volatile("ld.shared::cluster.f32 %0, [%1];"     : "=f"(pS) : "r"(raddr));
        asm volatile("ld.shared::cluster.f32 %0, [%1+4];"   : "=f"(pQ) : "r"(raddr));
        float S = s_cta[tid][0] + pS;
        float Q = s_cta[tid][1] + pQ;
        float mean = S * (1.f / 1024.f);
        float var  = Q * (1.f / 1024.f) - mean * mean;
        s_stats[tid][0] = mean;
        s_stats[tid][1] = rsqrtf(var + 1e-5f);
    }
    __syncthreads();

    // ---- normalize + write fp32 output directly ----
    #pragma unroll
    for (int mi = 0; mi < 4; ++mi){
        int row0 = mi * 16 + r_base;
        int row1 = row0 + 8;
        float mean0 = s_stats[row0][0], rstd0 = s_stats[row0][1];
        float mean1 = s_stats[row1][0], rstd1 = s_stats[row1][1];
        #pragma unroll
        for (int ni = 0; ni < 8; ++ni){
            int c = n0 + wn * 64 + ni * 8 + c_lane;
            float2 g  = ((const float2*)gamma)[c >> 1];
            float2 be = ((const float2*)beta)[c >> 1];
            float2 w0, w1;
            w0.x = (acc[mi][ni][0] - mean0) * rstd0 * g.x + be.x;
            w0.y = (acc[mi][ni][1] - mean0) * rstd0 * g.y + be.y;
            w1.x = (acc[mi][ni][2] - mean1) * rstd1 * g.x + be.x;
            w1.y = (acc[mi][ni][3] - mean1) * rstd1 * g.y + be.y;
            *(float2*)(out + (size_t)(m0 + row0) * FDIM + c) = w0;
            *(float2*)(out + (size_t)(m0 + row1) * FDIM + c) = w1;
        }
    }

    // exit safety: peer may still be reading our s_cta
    asm volatile("barrier.cluster.arrive.aligned;" ::: "memory");
    asm volatile("barrier.cluster.wait.aligned;"   ::: "memory");
}

// ---------------------------------------------------------------------------
// Launch
// ---------------------------------------------------------------------------
extern "C" void kernel_launch(void* const* d_in, const int* in_sizes, int n_in,
                              void* d_out, int out_size)
{
    (void)in_sizes; (void)n_in; (void)out_size;
    const float* x     = (const float*)d_in[0];
    const float* Wq    = (const float*)d_in[1];
    const float* bq    = (const float*)d_in[2];
    const float* Wk    = (const float*)d_in[3];
    const float* bk    = (const float*)d_in[4];
    const float* Wv    = (const float*)d_in[5];
    const float* bv    = (const float*)d_in[6];
    const float* Wo    = (const float*)d_in[7];
    const float* bo    = (const float*)d_in[8];
    const float* gamma = (const float*)d_in[9];
    const float* beta  = (const float*)d_in[10];
    float* out = (float*)d_out;

    cudaFuncSetAttribute(gemm1_kernel, cudaFuncAttributeMaxDynamicSharedMemorySize, GEMM_DSMEM);
    cudaFuncSetAttribute(gemm2_ln_kernel, cudaFuncAttributeMaxDynamicSharedMemorySize, G2_DSMEM);
    cudaFuncSetAttribute(attn_mma_kernel, cudaFuncAttributeMaxDynamicSharedMemorySize, ATTN_DSMEM);

    packb_kernel<<<12, 256>>>(bq, bk, bv);
    transw_kernel<<<dim3(32, 32, 4), dim3(32, 8)>>>(Wq, Wk, Wv, Wo);
    gemm1_kernel<<<dim3(NQKV / BN, TOKENS / BM), 256, GEMM_DSMEM>>>(x);
    attn_mma_kernel<<<TOKENS / 8, 256, ATTN_DSMEM>>>();
    gemm2_ln_kernel<<<dim3(FDIM / BN2, TOKENS / BM2), 256, G2_DSMEM>>>(bo, gamma, beta, out);
}

// round 11
// speedup vs baseline: 1.0670x; 1.0670x over previous
#include <cuda_runtime.h>
#include <cuda_fp16.h>
#include <cstdint>

// Problem constants
#define TOKENS 32768          // B*S = 16*2048
#define FDIM   1024
#define NQKV   3072
#define NHEAD  16
#define DHEAD  64

// ---------------------------------------------------------------------------
// Scratch (device globals; no allocations allowed)
// ---------------------------------------------------------------------------
__device__ __align__(16) half  g_Wqkv[(size_t)NQKV * FDIM];     // [N=3072, K=1024] transposed
__device__ __align__(16) half  g_Wo16[(size_t)FDIM * FDIM];     // [N=1024, K=1024] transposed
__device__ float               g_bqkv[NQKV];                    // packed biases
__device__ __align__(16) half  g_QKV [(size_t)TOKENS * NQKV];   // q,k,v per token
__device__ __align__(16) half  g_Attn[(size_t)TOKENS * FDIM];   // attention output
__device__ __align__(16) half  g_Z16 [(size_t)TOKENS * FDIM];   // pre-LN output (fp16)

// ---------------------------------------------------------------------------
// PTX helpers
// ---------------------------------------------------------------------------
__device__ __forceinline__ void cp_async16(void* dst, const void* src){
    unsigned s = (unsigned)__cvta_generic_to_shared(dst);
    asm volatile("cp.async.cg.shared.global [%0], [%1], 16;\n" :: "r"(s), "l"(src));
}
__device__ __forceinline__ void cp_commit(){ asm volatile("cp.async.commit_group;\n"); }
template<int N>
__device__ __forceinline__ void cp_wait(){ asm volatile("cp.async.wait_group %0;\n" :: "n"(N)); }

__device__ __forceinline__ void ldsm_x4(uint32_t* r, uint32_t addr){
    asm volatile("ldmatrix.sync.aligned.m8n8.x4.shared.b16 {%0,%1,%2,%3}, [%4];\n"
        : "=r"(r[0]), "=r"(r[1]), "=r"(r[2]), "=r"(r[3]) : "r"(addr));
}
__device__ __forceinline__ void ldsm_x4_t(uint32_t* r, uint32_t addr){
    asm volatile("ldmatrix.sync.aligned.m8n8.x4.trans.shared.b16 {%0,%1,%2,%3}, [%4];\n"
        : "=r"(r[0]), "=r"(r[1]), "=r"(r[2]), "=r"(r[3]) : "r"(addr));
}
__device__ __forceinline__ void mma16816(float* c, const uint32_t* a, const uint32_t* b){
    asm volatile("mma.sync.aligned.m16n8k16.row.col.f32.f16.f16.f32 "
        "{%0,%1,%2,%3}, {%4,%5,%6,%7}, {%8,%9}, {%0,%1,%2,%3};\n"
        : "+f"(c[0]), "+f"(c[1]), "+f"(c[2]), "+f"(c[3])
        : "r"(a[0]), "r"(a[1]), "r"(a[2]), "r"(a[3]), "r"(b[0]), "r"(b[1]));
}
__device__ __forceinline__ uint32_t h2_to_u32(half2 h){
    uint32_t u;
    memcpy(&u, &h, 4);
    return u;
}

// ---------------------------------------------------------------------------
// Pack biases
// ---------------------------------------------------------------------------
__global__ void __launch_bounds__(256) packb_kernel(
    const float* __restrict__ bq, const float* __restrict__ bk, const float* __restrict__ bv)
{
    int i = blockIdx.x * blockDim.x + threadIdx.x;
    if (i < NQKV)
        g_bqkv[i] = (i < 1024) ? bq[i] : (i < 2048) ? bk[i - 1024] : bv[i - 2048];
}

// ---------------------------------------------------------------------------
// Tiled transpose: W[k][n] fp32 -> Wt[n][k] fp16.  z: 0..2 -> Wqkv rows, 3 -> Wo
// ---------------------------------------------------------------------------
__global__ void __launch_bounds__(256) transw_kernel(
    const float* __restrict__ Wq, const float* __restrict__ Wk,
    const float* __restrict__ Wv, const float* __restrict__ Wo)
{
    __shared__ float t[32][33];
    const int z = blockIdx.z;
    const float* src = (z == 0) ? Wq : (z == 1) ? Wk : (z == 2) ? Wv : Wo;
    const int k0 = blockIdx.y * 32, n0 = blockIdx.x * 32;
    const int tx = threadIdx.x, ty = threadIdx.y;   // 32 x 8
    #pragma unroll
    for (int i = 0; i < 4; ++i)
        t[ty + i * 8][tx] = src[(size_t)(k0 + ty + i * 8) * FDIM + n0 + tx];
    __syncthreads();
    half* dst = (z < 3) ? (g_Wqkv + (size_t)z * FDIM * FDIM) : g_Wo16;
    #pragma unroll
    for (int i = 0; i < 4; ++i)
        dst[(size_t)(n0 + ty + i * 8) * FDIM + k0 + tx] = __float2half_rn(t[tx][ty + i * 8]);
}

// ---------------------------------------------------------------------------
// HMMA GEMM: C[M,NTOT] = A[M,1024] * B[NTOT,1024]^T + bias
//   CTA tile 128x256, 8 warps (2x4), warp tile 64x64, BK=64, 4-stage ring.
// MODE 0: A = x (fp32, converted inline), B=g_Wqkv, C=g_QKV, bias=g_bqkv
// MODE 1: A = g_Attn (fp16, cp.async), B=g_Wo16, C=g_Z16, bias=bias_ext
// ---------------------------------------------------------------------------
#define BM 128
#define BN 256
#define BK 64
#define SROW 72
#define A_ST_BYTES (BM * SROW * 2)
#define B_ST_BYTES (BN * SROW * 2)
#define STAGE_BYTES (A_ST_BYTES + B_ST_BYTES)
#define NSTAGES 4
#define NKBLK (FDIM / BK)
#define GEMM_DSMEM (NSTAGES * STAGE_BYTES)

template<int MODE>
__global__ void __launch_bounds__(256, 1) gemm_hmma_kernel(
    const float* __restrict__ xf, const float* __restrict__ bias_ext)
{
    constexpr int NTOT = (MODE == 0) ? NQKV : FDIM;
    const half* __restrict__ Bw = (MODE == 0) ? g_Wqkv : g_Wo16;

    extern __shared__ __align__(16) half sm[];

    const int tid  = threadIdx.x;
    const int lane = tid & 31;
    const int wid  = tid >> 5;
    const int wm   = wid & 1;
    const int wn   = wid >> 1;
    const int m0 = blockIdx.y * BM;
    const int n0 = blockIdx.x * BN;

    const float* Xbase = (MODE == 0) ? (xf + (size_t)m0 * FDIM) : nullptr;
    const half*  Abase = (MODE == 0) ? nullptr : (g_Attn + (size_t)m0 * FDIM);
    const half*  Bbase = Bw + (size_t)n0 * FDIM;

    float acc[4][8][4];
    #pragma unroll
    for (int mi = 0; mi < 4; ++mi)
        #pragma unroll
        for (int ni = 0; ni < 8; ++ni)
            #pragma unroll
            for (int t = 0; t < 4; ++t) acc[mi][ni][t] = 0.f;

    auto loadB = [&](int s){
        const int buf = s & (NSTAGES - 1);
        half* bs = sm + (size_t)buf * (STAGE_BYTES / 2) + (A_ST_BYTES / 2);
        const half* Bsrc = Bbase + s * BK;
        #pragma unroll
        for (int i = 0; i < 8; ++i){
            int idx = tid + i * 256;
            int r = idx >> 3, c = idx & 7;
            cp_async16(bs + r * SROW + c * 8, Bsrc + (size_t)r * FDIM + c * 8);
        }
        cp_commit();
    };
    auto loadA_async = [&](int s){
        const int buf = s & (NSTAGES - 1);
        half* as = sm + (size_t)buf * (STAGE_BYTES / 2);
        const half* Asrc = Abase + s * BK;
        #pragma unroll
        for (int i = 0; i < 4; ++i){
            int idx = tid + i * 256;
            int r = idx >> 3, c = idx & 7;
            cp_async16(as + r * SROW + c * 8, Asrc + (size_t)r * FDIM + c * 8);
        }
    };
    auto ldgA = [&](int s, float4* ar){
        const float* Asrc = Xbase + s * BK;
        #pragma unroll
        for (int i = 0; i < 4; ++i){
            int idx = tid + i * 256;
            int r = idx >> 3, c = idx & 7;
            const float4* p = (const float4*)(Asrc + (size_t)r * FDIM + c * 8);
            ar[2 * i]     = p[0];
            ar[2 * i + 1] = p[1];
        }
    };
    auto stsA = [&](int s, const float4* ar){
        const int buf = s & (NSTAGES - 1);
        half* as = sm + (size_t)buf * (STAGE_BYTES / 2);
        #pragma unroll
        for (int i = 0; i < 4; ++i){
            int idx = tid + i * 256;
            int r = idx >> 3, c = idx & 7;
            float4 a0 = ar[2 * i], a1 = ar[2 * i + 1];
            uint4 packed;
            packed.x = h2_to_u32(__floats2half2_rn(a0.x, a0.y));
            packed.y = h2_to_u32(__floats2half2_rn(a0.z, a0.w));
            packed.z = h2_to_u32(__floats2half2_rn(a1.x, a1.y));
            packed.w = h2_to_u32(__floats2half2_rn(a1.z, a1.w));
            *(uint4*)(as + r * SROW + c * 8) = packed;
        }
    };

    #pragma unroll
    for (int s = 0; s < 3; ++s){
        if constexpr (MODE == 0){
            float4 ar[8];
            ldgA(s, ar);
            stsA(s, ar);
        } else {
            loadA_async(s);
        }
        loadB(s);
    }

    const int a_row = wm * 64 + (lane & 15);
    const int a_colb = (lane >> 4) << 3;
    const int b_row = wn * 64 + (lane & 7) + ((lane >> 4) << 3);
    const int b_colb = ((lane >> 3) & 1) << 3;

    for (int s = 0; s < NKBLK; ++s){
        const bool pre = (s + 3 < NKBLK);
        float4 ar[8];
        if constexpr (MODE == 0){
            if (pre) ldgA(s + 3, ar);
        }

        const int rem = (NKBLK - 1) - s;
        if (rem >= 2)      cp_wait<2>();
        else if (rem == 1) cp_wait<1>();
        else               cp_wait<0>();
        __syncthreads();

        if (pre){
            if constexpr (MODE == 1) loadA_async(s + 3);
            loadB(s + 3);
        }

        const int buf = s & (NSTAGES - 1);
        const half* as = sm + (size_t)buf * (STAGE_BYTES / 2);
        const half* bs = as + (A_ST_BYTES / 2);
        const uint32_t aB = (uint32_t)__cvta_generic_to_shared(as);
        const uint32_t bB = (uint32_t)__cvta_generic_to_shared(bs);

        #pragma unroll
        for (int kk = 0; kk < 4; ++kk){
            const int k16 = kk * 16;
            uint32_t a[4][4], b[8][2];
            #pragma unroll
            for (int mi = 0; mi < 4; ++mi){
                uint32_t addr = aB + (uint32_t)(((a_row + mi * 16) * SROW + k16 + a_colb) * 2);
                ldsm_x4(&a[mi][0], addr);
            }
            #pragma unroll
            for (int nb = 0; nb < 4; ++nb){
                uint32_t addr = bB + (uint32_t)(((b_row + nb * 16) * SROW + k16 + b_colb) * 2);
                uint32_t r[4];
                ldsm_x4(r, addr);
                b[nb * 2][0] = r[0];     b[nb * 2][1] = r[1];
                b[nb * 2 + 1][0] = r[2]; b[nb * 2 + 1][1] = r[3];
            }
            #pragma unroll
            for (int mi = 0; mi < 4; ++mi)
                #pragma unroll
                for (int ni = 0; ni < 8; ++ni)
                    mma16816(acc[mi][ni], a[mi], b[ni]);
        }

        if constexpr (MODE == 0){
            if (pre) stsA(s + 3, ar);
        }
    }

    const float* bias = (MODE == 0) ? g_bqkv : bias_ext;
    #pragma unroll
    for (int mi = 0; mi < 4; ++mi){
        #pragma unroll
        for (int ni = 0; ni < 8; ++ni){
            int r = m0 + wm * 64 + mi * 16 + (lane >> 2);
            int c = n0 + wn * 64 + ni * 8 + ((lane & 3) << 1);
            float b0 = bias[c], b1 = bias[c + 1];
            float v0 = acc[mi][ni][0] + b0, v1 = acc[mi][ni][1] + b1;
            float v2 = acc[mi][ni][2] + b0, v3 = acc[mi][ni][3] + b1;
            half* dst = (MODE == 0) ? g_QKV : g_Z16;
            *(half2*)(dst + (size_t)r * NTOT + c)       = __floats2half2_rn(v0, v1);
            *(half2*)(dst + (size_t)(r + 8) * NTOT + c) = __floats2half2_rn(v2, v3);
        }
    }
}

// ---------------------------------------------------------------------------
// Tensor-core per-token attention. 1 warp per token, 8 tokens per block.
// ---------------------------------------------------------------------------
#define ATOK_ROWS 48
#define ATOK_H (ATOK_ROWS * 72)            // 3456 halfs per token
#define ATTN_DSMEM (8 * ATOK_H * 2)        // 55296 bytes

__global__ void __launch_bounds__(256) attn_mma_kernel(){
    extern __shared__ __align__(16) half sm_a[];
    const int tid = threadIdx.x, lane = tid & 31, w = tid >> 5;
    const size_t tok0 = (size_t)blockIdx.x * 8;

    {
        const half* src = g_QKV + tok0 * NQKV;
        #pragma unroll
        for (int i = 0; i < 12; ++i){
            int idx = tid + i * 256;
            int tok = idx / 384, j = idx - tok * 384;
            int row = j >> 3, c = j & 7;
            cp_async16(sm_a + tok * ATOK_H + row * 72 + c * 8,
                       src + (size_t)tok * NQKV + j * 8);
        }
        cp_commit();
        cp_wait<0>();
    }
    __syncthreads();

    half* base = sm_a + w * ATOK_H;
    const uint32_t sb = (uint32_t)__cvta_generic_to_shared(base);

    float e0[4] = {0,0,0,0}, e1[4] = {0,0,0,0};
    {
        const int q_row  = lane & 15;
        const int q_colb = (lane >> 4) << 3;
        const int k_row  = 16 + (lane & 7) + ((lane >> 4) << 3);
        const int k_colb = ((lane >> 3) & 1) << 3;
        #pragma unroll
        for (int kc = 0; kc < 4; ++kc){
            const int k16 = kc * 16;
            uint32_t qa[4], kr[4];
            ldsm_x4(qa, sb + (uint32_t)((q_row * 72 + k16 + q_colb) * 2));
            ldsm_x4(kr, sb + (uint32_t)((k_row * 72 + k16 + k_colb) * 2));
            mma16816(e0, qa, &kr[0]);
            mma16816(e1, qa, &kr[2]);
        }
    }

    {
        const float sc = 0.125f;
        e0[0]*=sc; e0[1]*=sc; e0[2]*=sc; e0[3]*=sc;
        e1[0]*=sc; e1[1]*=sc; e1[2]*=sc; e1[3]*=sc;
        float mA = fmaxf(fmaxf(e0[0], e0[1]), fmaxf(e1[0], e1[1]));
        float mB = fmaxf(fmaxf(e0[2], e0[3]), fmaxf(e1[2], e1[3]));
        mA = fmaxf(mA, __shfl_xor_sync(0xffffffffu, mA, 1));
        mA = fmaxf(mA, __shfl_xor_sync(0xffffffffu, mA, 2));
        mB = fmaxf(mB, __shfl_xor_sync(0xffffffffu, mB, 1));
        mB = fmaxf(mB, __shfl_xor_sync(0xffffffffu, mB, 2));
        e0[0] = __expf(e0[0] - mA); e0[1] = __expf(e0[1] - mA);
        e1[0] = __expf(e1[0] - mA); e1[1] = __expf(e1[1] - mA);
        e0[2] = __expf(e0[2] - mB); e0[3] = __expf(e0[3] - mB);
        e1[2] = __expf(e1[2] - mB); e1[3] = __expf(e1[3] - mB);
        float sA = e0[0] + e0[1] + e1[0] + e1[1];
        float sB = e0[2] + e0[3] + e1[2] + e1[3];
        sA += __shfl_xor_sync(0xffffffffu, sA, 1);
        sA += __shfl_xor_sync(0xffffffffu, sA, 2);
        sB += __shfl_xor_sync(0xffffffffu, sB, 1);
        sB += __shfl_xor_sync(0xffffffffu, sB, 2);
        float iA = 1.f / sA, iB = 1.f / sB;
        e0[0]*=iA; e0[1]*=iA; e1[0]*=iA; e1[1]*=iA;
        e0[2]*=iB; e0[3]*=iB; e1[2]*=iB; e1[3]*=iB;
    }

    uint32_t pa[4];
    pa[0] = h2_to_u32(__floats2half2_rn(e0[0], e0[1]));
    pa[1] = h2_to_u32(__floats2half2_rn(e0[2], e0[3]));
    pa[2] = h2_to_u32(__floats2half2_rn(e1[0], e1[1]));
    pa[3] = h2_to_u32(__floats2half2_rn(e1[2], e1[3]));

    float o[8][4];
    #pragma unroll
    for (int nt = 0; nt < 8; ++nt){ o[nt][0]=0; o[nt][1]=0; o[nt][2]=0; o[nt][3]=0; }
    {
        const int v_row = 32 + (lane & 15);
        #pragma unroll
        for (int i = 0; i < 4; ++i){
            const int db = i * 16;
            uint32_t vr[4];
            ldsm_x4_t(vr, sb + (uint32_t)((v_row * 72 + db + ((lane >> 4) << 3)) * 2));
            mma16816(o[i * 2],     pa, &vr[0]);
            mma16816(o[i * 2 + 1], pa, &vr[2]);
        }
    }

    {
        const int r = lane >> 2;
        const int c2 = (lane & 3) << 1;
        #pragma unroll
        for (int nt = 0; nt < 8; ++nt){
            *(half2*)(base + r * 72 + nt * 8 + c2)       = __floats2half2_rn(o[nt][0], o[nt][1]);
            *(half2*)(base + (r + 8) * 72 + nt * 8 + c2) = __floats2half2_rn(o[nt][2], o[nt][3]);
        }
    }
    __syncthreads();

    {
        float4* gout = (float4*)(g_Attn + tok0 * FDIM);
        #pragma unroll
        for (int i = 0; i < 4; ++i){
            int idx = tid + i * 256;
            int tok = idx >> 7, j = idx & 127;
            int row = j >> 3, c = j & 7;
            gout[(size_t)tok * 128 + j] = *(const float4*)(sm_a + tok * ATOK_H + row * 72 + c * 8);
        }
    }
}

// ---------------------------------------------------------------------------
// LayerNorm, warp-per-row: 8 rows per 256-thread block, pure shfl reduction.
// Each lane holds 32 consecutive-by-chunk values (4x LDG.128), normalizes in
// registers, writes 8x STG.128. No smem, no block barrier.
// ---------------------------------------------------------------------------
__global__ void __launch_bounds__(256) ln_kernel(const float* __restrict__ gamma,
                                                 const float* __restrict__ beta,
                                                 float* __restrict__ out)
{
    const int lane = threadIdx.x & 31, w = threadIdx.x >> 5;
    const size_t row = (size_t)blockIdx.x * 8 + w;
    const half* zrow = g_Z16 + row * FDIM;

    float v[32];
    #pragma unroll
    for (int k = 0; k < 4; ++k){
        uint4 raw = ((const uint4*)zrow)[lane + k * 32];   // 8 halfs
        half2 h;
        float2 f;
        memcpy(&h, &raw.x, 4); f = __half22float2(h); v[k*8+0] = f.x; v[k*8+1] = f.y;
        memcpy(&h, &raw.y, 4); f = __half22float2(h); v[k*8+2] = f.x; v[k*8+3] = f.y;
        memcpy(&h, &raw.z, 4); f = __half22float2(h); v[k*8+4] = f.x; v[k*8+5] = f.y;
        memcpy(&h, &raw.w, 4); f = __half22float2(h); v[k*8+6] = f.x; v[k*8+7] = f.y;
    }

    float s = 0.f, q = 0.f;
    #pragma unroll
    for (int i = 0; i < 32; ++i){ s += v[i]; q += v[i] * v[i]; }
    #pragma unroll
    for (int o = 16; o > 0; o >>= 1){
        s += __shfl_xor_sync(0xffffffffu, s, o);
        q += __shfl_xor_sync(0xffffffffu, q, o);
    }
    const float mean = s * (1.f / 1024.f);
    const float rstd = rsqrtf(q * (1.f / 1024.f) - mean * mean + 1e-5f);

    float* orow = out + row * FDIM;
    #pragma unroll
    for (int k = 0; k < 4; ++k){
        const int cg = lane + k * 32;      // 8-half column group
        #pragma unroll
        for (int h = 0; h < 2; ++h){
            const int f4 = cg * 2 + h;     // float4 index (4 floats)
            float4 g4 = ((const float4*)gamma)[f4];
            float4 b4 = ((const float4*)beta)[f4];
            float4 r;
            r.x = (v[k*8 + h*4 + 0] - mean) * rstd * g4.x + b4.x;
            r.y = (v[k*8 + h*4 + 1] - mean) * rstd * g4.y + b4.y;
            r.z = (v[k*8 + h*4 + 2] - mean) * rstd * g4.z + b4.z;
            r.w = (v[k*8 + h*4 + 3] - mean) * rstd * g4.w + b4.w;
            ((float4*)orow)[f4] = r;
        }
    }
}

// ---------------------------------------------------------------------------
// Launch
// ---------------------------------------------------------------------------
extern "C" void kernel_launch(void* const* d_in, const int* in_sizes, int n_in,
                              void* d_out, int out_size)
{
    (void)in_sizes; (void)n_in; (void)out_size;
    const float* x     = (const float*)d_in[0];
    const float* Wq    = (const float*)d_in[1];
    const float* bq    = (const float*)d_in[2];
    const float* Wk    = (const float*)d_in[3];
    const float* bk    = (const float*)d_in[4];
    const float* Wv    = (const float*)d_in[5];
    const float* bv    = (const float*)d_in[6];
    const float* Wo    = (const float*)d_in[7];
    const float* bo    = (const float*)d_in[8];
    const float* gamma = (const float*)d_in[9];
    const float* beta  = (const float*)d_in[10];
    float* out = (float*)d_out;

    cudaFuncSetAttribute(gemm_hmma_kernel<0>, cudaFuncAttributeMaxDynamicSharedMemorySize, GEMM_DSMEM);
    cudaFuncSetAttribute(gemm_hmma_kernel<1>, cudaFuncAttributeMaxDynamicSharedMemorySize, GEMM_DSMEM);
    cudaFuncSetAttribute(attn_mma_kernel, cudaFuncAttributeMaxDynamicSharedMemorySize, ATTN_DSMEM);

    packb_kernel<<<12, 256>>>(bq, bk, bv);
    transw_kernel<<<dim3(32, 32, 4), dim3(32, 8)>>>(Wq, Wk, Wv, Wo);
    gemm_hmma_kernel<0><<<dim3(NQKV / BN, TOKENS / BM), 256, GEMM_DSMEM>>>(x, nullptr);
    attn_mma_kernel<<<TOKENS / 8, 256, ATTN_DSMEM>>>();
    gemm_hmma_kernel<1><<<dim3(FDIM / BN, TOKENS / BM), 256, GEMM_DSMEM>>>(nullptr, bo);
    ln_kernel<<<TOKENS / 8, 256>>>(gamma, beta, out);
}

// round 12
// speedup vs baseline: 1.0778x; 1.0101x over previous
#include <cuda_runtime.h>
#include <cuda_fp16.h>
#include <cstdint>

// Problem constants
#define TOKENS 32768          // B*S = 16*2048
#define FDIM   1024
#define NQKV   3072
#define NHEAD  16
#define DHEAD  64

// ---------------------------------------------------------------------------
// Scratch (device globals; no allocations allowed)
// ---------------------------------------------------------------------------
__device__ __align__(16) half  g_Wqkv[(size_t)NQKV * FDIM];     // [N=3072, K=1024] transposed
__device__ __align__(16) half  g_Wo16[(size_t)FDIM * FDIM];     // [N=1024, K=1024] transposed
__device__ float               g_bqkv[NQKV];                    // packed biases
__device__ __align__(16) half  g_QKV [(size_t)TOKENS * NQKV];   // q,k,v per token
__device__ __align__(16) half  g_Attn[(size_t)TOKENS * FDIM];   // attention output
__device__ __align__(16) half  g_Z16 [(size_t)TOKENS * FDIM];   // pre-LN output (fp16)

// ---------------------------------------------------------------------------
// PTX helpers
// ---------------------------------------------------------------------------
__device__ __forceinline__ void cp_async16(void* dst, const void* src){
    unsigned s = (unsigned)__cvta_generic_to_shared(dst);
    asm volatile("cp.async.cg.shared.global [%0], [%1], 16;\n" :: "r"(s), "l"(src));
}
__device__ __forceinline__ void cp_commit(){ asm volatile("cp.async.commit_group;\n"); }
template<int N>
__device__ __forceinline__ void cp_wait(){ asm volatile("cp.async.wait_group %0;\n" :: "n"(N)); }

__device__ __forceinline__ void ldsm_x4(uint32_t* r, uint32_t addr){
    asm volatile("ldmatrix.sync.aligned.m8n8.x4.shared.b16 {%0,%1,%2,%3}, [%4];\n"
        : "=r"(r[0]), "=r"(r[1]), "=r"(r[2]), "=r"(r[3]) : "r"(addr));
}
__device__ __forceinline__ void ldsm_x4_t(uint32_t* r, uint32_t addr){
    asm volatile("ldmatrix.sync.aligned.m8n8.x4.trans.shared.b16 {%0,%1,%2,%3}, [%4];\n"
        : "=r"(r[0]), "=r"(r[1]), "=r"(r[2]), "=r"(r[3]) : "r"(addr));
}
__device__ __forceinline__ void mma16816(float* c, const uint32_t* a, const uint32_t* b){
    asm volatile("mma.sync.aligned.m16n8k16.row.col.f32.f16.f16.f32 "
        "{%0,%1,%2,%3}, {%4,%5,%6,%7}, {%8,%9}, {%0,%1,%2,%3};\n"
        : "+f"(c[0]), "+f"(c[1]), "+f"(c[2]), "+f"(c[3])
        : "r"(a[0]), "r"(a[1]), "r"(a[2]), "r"(a[3]), "r"(b[0]), "r"(b[1]));
}
__device__ __forceinline__ uint32_t h2_to_u32(half2 h){
    uint32_t u;
    memcpy(&u, &h, 4);
    return u;
}

// ---------------------------------------------------------------------------
// Tiled transpose: W[k][n] fp32 -> Wt[n][k] fp16.  z: 0..2 -> Wqkv rows, 3 -> Wo
// The (31,31) block of each z<3 slice also packs that matrix's bias into g_bqkv.
// ---------------------------------------------------------------------------
__global__ void __launch_bounds__(256) transw_kernel(
    const float* __restrict__ Wq, const float* __restrict__ Wk,
    const float* __restrict__ Wv, const float* __restrict__ Wo,
    const float* __restrict__ bq, const float* __restrict__ bk,
    const float* __restrict__ bv)
{
    __shared__ float t[32][33];
    const int z = blockIdx.z;
    const float* src = (z == 0) ? Wq : (z == 1) ? Wk : (z == 2) ? Wv : Wo;
    const int k0 = blockIdx.y * 32, n0 = blockIdx.x * 32;
    const int tx = threadIdx.x, ty = threadIdx.y;   // 32 x 8
    #pragma unroll
    for (int i = 0; i < 4; ++i)
        t[ty + i * 8][tx] = src[(size_t)(k0 + ty + i * 8) * FDIM + n0 + tx];
    __syncthreads();
    half* dst = (z < 3) ? (g_Wqkv + (size_t)z * FDIM * FDIM) : g_Wo16;
    #pragma unroll
    for (int i = 0; i < 4; ++i)
        dst[(size_t)(n0 + ty + i * 8) * FDIM + k0 + tx] = __float2half_rn(t[tx][ty + i * 8]);

    if (z < 3 && blockIdx.x == 31 && blockIdx.y == 31){
        const float* b = (z == 0) ? bq : (z == 1) ? bk : bv;
        const int tid = ty * 32 + tx;
        #pragma unroll
        for (int i = 0; i < 4; ++i)
            g_bqkv[z * 1024 + tid + i * 256] = b[tid + i * 256];
    }
}

// ---------------------------------------------------------------------------
// HMMA GEMM: C[M,NTOT] = A[M,1024] * B[NTOT,1024]^T + bias
//   CTA tile 128x256, 8 warps (2x4), warp tile 64x64, BK=64, 4-stage ring.
// MODE 0: A = x (fp32, converted inline), B=g_Wqkv, C=g_QKV, bias=g_bqkv
// MODE 1: A = g_Attn (fp16, cp.async), B=g_Wo16, C=g_Z16, bias=bias_ext
// ---------------------------------------------------------------------------
#define BM 128
#define BN 256
#define BK 64
#define SROW 72
#define A_ST_BYTES (BM * SROW * 2)
#define B_ST_BYTES (BN * SROW * 2)
#define STAGE_BYTES (A_ST_BYTES + B_ST_BYTES)
#define NSTAGES 4
#define NKBLK (FDIM / BK)
#define GEMM_DSMEM (NSTAGES * STAGE_BYTES)

template<int MODE>
__global__ void __launch_bounds__(256, 1) gemm_hmma_kernel(
    const float* __restrict__ xf, const float* __restrict__ bias_ext)
{
    constexpr int NTOT = (MODE == 0) ? NQKV : FDIM;
    const half* __restrict__ Bw = (MODE == 0) ? g_Wqkv : g_Wo16;

    extern __shared__ __align__(16) half sm[];

    const int tid  = threadIdx.x;
    const int lane = tid & 31;
    const int wid  = tid >> 5;
    const int wm   = wid & 1;
    const int wn   = wid >> 1;
    const int m0 = blockIdx.y * BM;
    const int n0 = blockIdx.x * BN;

    const float* Xbase = (MODE == 0) ? (xf + (size_t)m0 * FDIM) : nullptr;
    const half*  Abase = (MODE == 0) ? nullptr : (g_Attn + (size_t)m0 * FDIM);
    const half*  Bbase = Bw + (size_t)n0 * FDIM;

    float acc[4][8][4];
    #pragma unroll
    for (int mi = 0; mi < 4; ++mi)
        #pragma unroll
        for (int ni = 0; ni < 8; ++ni)
            #pragma unroll
            for (int t = 0; t < 4; ++t) acc[mi][ni][t] = 0.f;

    auto loadB = [&](int s){
        const int buf = s & (NSTAGES - 1);
        half* bs = sm + (size_t)buf * (STAGE_BYTES / 2) + (A_ST_BYTES / 2);
        const half* Bsrc = Bbase + s * BK;
        #pragma unroll
        for (int i = 0; i < 8; ++i){
            int idx = tid + i * 256;
            int r = idx >> 3, c = idx & 7;
            cp_async16(bs + r * SROW + c * 8, Bsrc + (size_t)r * FDIM + c * 8);
        }
        cp_commit();
    };
    auto loadA_async = [&](int s){
        const int buf = s & (NSTAGES - 1);
        half* as = sm + (size_t)buf * (STAGE_BYTES / 2);
        const half* Asrc = Abase + s * BK;
        #pragma unroll
        for (int i = 0; i < 4; ++i){
            int idx = tid + i * 256;
            int r = idx >> 3, c = idx & 7;
            cp_async16(as + r * SROW + c * 8, Asrc + (size_t)r * FDIM + c * 8);
        }
    };
    auto ldgA = [&](int s, float4* ar){
        const float* Asrc = Xbase + s * BK;
        #pragma unroll
        for (int i = 0; i < 4; ++i){
            int idx = tid + i * 256;
            int r = idx >> 3, c = idx & 7;
            const float4* p = (const float4*)(Asrc + (size_t)r * FDIM + c * 8);
            ar[2 * i]     = p[0];
            ar[2 * i + 1] = p[1];
        }
    };
    auto stsA = [&](int s, const float4* ar){
        const int buf = s & (NSTAGES - 1);
        half* as = sm + (size_t)buf * (STAGE_BYTES / 2);
        #pragma unroll
        for (int i = 0; i < 4; ++i){
            int idx = tid + i * 256;
            int r = idx >> 3, c = idx & 7;
            float4 a0 = ar[2 * i], a1 = ar[2 * i + 1];
            uint4 packed;
            packed.x = h2_to_u32(__floats2half2_rn(a0.x, a0.y));
            packed.y = h2_to_u32(__floats2half2_rn(a0.z, a0.w));
            packed.z = h2_to_u32(__floats2half2_rn(a1.x, a1.y));
            packed.w = h2_to_u32(__floats2half2_rn(a1.z, a1.w));
            *(uint4*)(as + r * SROW + c * 8) = packed;
        }
    };

    #pragma unroll
    for (int s = 0; s < 3; ++s){
        if constexpr (MODE == 0){
            float4 ar[8];
            ldgA(s, ar);
            stsA(s, ar);
        } else {
            loadA_async(s);
        }
        loadB(s);
    }

    const int a_row = wm * 64 + (lane & 15);
    const int a_colb = (lane >> 4) << 3;
    const int b_row = wn * 64 + (lane & 7) + ((lane >> 4) << 3);
    const int b_colb = ((lane >> 3) & 1) << 3;

    for (int s = 0; s < NKBLK; ++s){
        const bool pre = (s + 3 < NKBLK);
        float4 ar[8];
        if constexpr (MODE == 0){
            if (pre) ldgA(s + 3, ar);
        }

        const int rem = (NKBLK - 1) - s;
        if (rem >= 2)      cp_wait<2>();
        else if (rem == 1) cp_wait<1>();
        else               cp_wait<0>();
        __syncthreads();

        if (pre){
            if constexpr (MODE == 1) loadA_async(s + 3);
            loadB(s + 3);
        }

        const int buf = s & (NSTAGES - 1);
        const half* as = sm + (size_t)buf * (STAGE_BYTES / 2);
        const half* bs = as + (A_ST_BYTES / 2);
        const uint32_t aB = (uint32_t)__cvta_generic_to_shared(as);
        const uint32_t bB = (uint32_t)__cvta_generic_to_shared(bs);

        #pragma unroll
        for (int kk = 0; kk < 4; ++kk){
            const int k16 = kk * 16;
            uint32_t a[4][4], b[8][2];
            #pragma unroll
            for (int mi = 0; mi < 4; ++mi){
                uint32_t addr = aB + (uint32_t)(((a_row + mi * 16) * SROW + k16 + a_colb) * 2);
                ldsm_x4(&a[mi][0], addr);
            }
            #pragma unroll
            for (int nb = 0; nb < 4; ++nb){
                uint32_t addr = bB + (uint32_t)(((b_row + nb * 16) * SROW + k16 + b_colb) * 2);
                uint32_t r[4];
                ldsm_x4(r, addr);
                b[nb * 2][0] = r[0];     b[nb * 2][1] = r[1];
                b[nb * 2 + 1][0] = r[2]; b[nb * 2 + 1][1] = r[3];
            }
            #pragma unroll
            for (int mi = 0; mi < 4; ++mi)
                #pragma unroll
                for (int ni = 0; ni < 8; ++ni)
                    mma16816(acc[mi][ni], a[mi], b[ni]);
        }

        if constexpr (MODE == 0){
            if (pre) stsA(s + 3, ar);
        }
    }

    const float* bias = (MODE == 0) ? g_bqkv : bias_ext;
    #pragma unroll
    for (int mi = 0; mi < 4; ++mi){
        #pragma unroll
        for (int ni = 0; ni < 8; ++ni){
            int r = m0 + wm * 64 + mi * 16 + (lane >> 2);
            int c = n0 + wn * 64 + ni * 8 + ((lane & 3) << 1);
            float b0 = bias[c], b1 = bias[c + 1];
            float v0 = acc[mi][ni][0] + b0, v1 = acc[mi][ni][1] + b1;
            float v2 = acc[mi][ni][2] + b0, v3 = acc[mi][ni][3] + b1;
            half* dst = (MODE == 0) ? g_QKV : g_Z16;
            *(half2*)(dst + (size_t)r * NTOT + c)       = __floats2half2_rn(v0, v1);
            *(half2*)(dst + (size_t)(r + 8) * NTOT + c) = __floats2half2_rn(v2, v3);
        }
    }
}

// ---------------------------------------------------------------------------
// Tensor-core per-token attention. 1 warp per token, 8 tokens per block.
// ---------------------------------------------------------------------------
#define ATOK_ROWS 48
#define ATOK_H (ATOK_ROWS * 72)            // 3456 halfs per token
#define ATTN_DSMEM (8 * ATOK_H * 2)        // 55296 bytes

__global__ void __launch_bounds__(256) attn_mma_kernel(){
    extern __shared__ __align__(16) half sm_a[];
    const int tid = threadIdx.x, lane = tid & 31, w = tid >> 5;
    const size_t tok0 = (size_t)blockIdx.x * 8;

    {
        const half* src = g_QKV + tok0 * NQKV;
        #pragma unroll
        for (int i = 0; i < 12; ++i){
            int idx = tid + i * 256;
            int tok = idx / 384, j = idx - tok * 384;
            int row = j >> 3, c = j & 7;
            cp_async16(sm_a + tok * ATOK_H + row * 72 + c * 8,
                       src + (size_t)tok * NQKV + j * 8);
        }
        cp_commit();
        cp_wait<0>();
    }
    __syncthreads();

    half* base = sm_a + w * ATOK_H;
    const uint32_t sb = (uint32_t)__cvta_generic_to_shared(base);

    float e0[4] = {0,0,0,0}, e1[4] = {0,0,0,0};
    {
        const int q_row  = lane & 15;
        const int q_colb = (lane >> 4) << 3;
        const int k_row  = 16 + (lane & 7) + ((lane >> 4) << 3);
        const int k_colb = ((lane >> 3) & 1) << 3;
        #pragma unroll
        for (int kc = 0; kc < 4; ++kc){
            const int k16 = kc * 16;
            uint32_t qa[4], kr[4];
            ldsm_x4(qa, sb + (uint32_t)((q_row * 72 + k16 + q_colb) * 2));
            ldsm_x4(kr, sb + (uint32_t)((k_row * 72 + k16 + k_colb) * 2));
            mma16816(e0, qa, &kr[0]);
            mma16816(e1, qa, &kr[2]);
        }
    }

    {
        const float sc = 0.125f;
        e0[0]*=sc; e0[1]*=sc; e0[2]*=sc; e0[3]*=sc;
        e1[0]*=sc; e1[1]*=sc; e1[2]*=sc; e1[3]*=sc;
        float mA = fmaxf(fmaxf(e0[0], e0[1]), fmaxf(e1[0], e1[1]));
        float mB = fmaxf(fmaxf(e0[2], e0[3]), fmaxf(e1[2], e1[3]));
        mA = fmaxf(mA, __shfl_xor_sync(0xffffffffu, mA, 1));
        mA = fmaxf(mA, __shfl_xor_sync(0xffffffffu, mA, 2));
        mB = fmaxf(mB, __shfl_xor_sync(0xffffffffu, mB, 1));
        mB = fmaxf(mB, __shfl_xor_sync(0xffffffffu, mB, 2));
        e0[0] = __expf(e0[0] - mA); e0[1] = __expf(e0[1] - mA);
        e1[0] = __expf(e1[0] - mA); e1[1] = __expf(e1[1] - mA);
        e0[2] = __expf(e0[2] - mB); e0[3] = __expf(e0[3] - mB);
        e1[2] = __expf(e1[2] - mB); e1[3] = __expf(e1[3] - mB);
        float sA = e0[0] + e0[1] + e1[0] + e1[1];
        float sB = e0[2] + e0[3] + e1[2] + e1[3];
        sA += __shfl_xor_sync(0xffffffffu, sA, 1);
        sA += __shfl_xor_sync(0xffffffffu, sA, 2);
        sB += __shfl_xor_sync(0xffffffffu, sB, 1);
        sB += __shfl_xor_sync(0xffffffffu, sB, 2);
        float iA = 1.f / sA, iB = 1.f / sB;
        e0[0]*=iA; e0[1]*=iA; e1[0]*=iA; e1[1]*=iA;
        e0[2]*=iB; e0[3]*=iB; e1[2]*=iB; e1[3]*=iB;
    }

    uint32_t pa[4];
    pa[0] = h2_to_u32(__floats2half2_rn(e0[0], e0[1]));
    pa[1] = h2_to_u32(__floats2half2_rn(e0[2], e0[3]));
    pa[2] = h2_to_u32(__floats2half2_rn(e1[0], e1[1]));
    pa[3] = h2_to_u32(__floats2half2_rn(e1[2], e1[3]));

    float o[8][4];
    #pragma unroll
    for (int nt = 0; nt < 8; ++nt){ o[nt][0]=0; o[nt][1]=0; o[nt][2]=0; o[nt][3]=0; }
    {
        const int v_row = 32 + (lane & 15);
        #pragma unroll
        for (int i = 0; i < 4; ++i){
            const int db = i * 16;
            uint32_t vr[4];
            ldsm_x4_t(vr, sb + (uint32_t)((v_row * 72 + db + ((lane >> 4) << 3)) * 2));
            mma16816(o[i * 2],     pa, &vr[0]);
            mma16816(o[i * 2 + 1], pa, &vr[2]);
        }
    }

    {
        const int r = lane >> 2;
        const int c2 = (lane & 3) << 1;
        #pragma unroll
        for (int nt = 0; nt < 8; ++nt){
            *(half2*)(base + r * 72 + nt * 8 + c2)       = __floats2half2_rn(o[nt][0], o[nt][1]);
            *(half2*)(base + (r + 8) * 72 + nt * 8 + c2) = __floats2half2_rn(o[nt][2], o[nt][3]);
        }
    }
    __syncthreads();

    {
        float4* gout = (float4*)(g_Attn + tok0 * FDIM);
        #pragma unroll
        for (int i = 0; i < 4; ++i){
            int idx = tid + i * 256;
            int tok = idx >> 7, j = idx & 127;
            int row = j >> 3, c = j & 7;
            gout[(size_t)tok * 128 + j] = *(const float4*)(sm_a + tok * ATOK_H + row * 72 + c * 8);
        }
    }
}

// ---------------------------------------------------------------------------
// LayerNorm, warp-per-row, fully coalesced:
//   loads: uint2 (4 halfs) at half-index (lane + j*32)*4  -> 256B per warp wave
//   stores: float4 at index (lane + j*32)                 -> 512B per warp wave
// ---------------------------------------------------------------------------
__global__ void __launch_bounds__(256) ln_kernel(const float* __restrict__ gamma,
                                                 const float* __restrict__ beta,
                                                 float* __restrict__ out)
{
    const int lane = threadIdx.x & 31, w = threadIdx.x >> 5;
    const size_t row = (size_t)blockIdx.x * 8 + w;
    const half* zrow = g_Z16 + row * FDIM;

    float v[32];
    #pragma unroll
    for (int j = 0; j < 8; ++j){
        uint2 raw = ((const uint2*)zrow)[lane + j * 32];   // 4 halfs
        half2 h01, h23;
        memcpy(&h01, &raw.x, 4);
        memcpy(&h23, &raw.y, 4);
        float2 f01 = __half22float2(h01), f23 = __half22float2(h23);
        v[j*4 + 0] = f01.x; v[j*4 + 1] = f01.y;
        v[j*4 + 2] = f23.x; v[j*4 + 3] = f23.y;
    }

    float s = 0.f, q = 0.f;
    #pragma unroll
    for (int i = 0; i < 32; ++i){ s += v[i]; q += v[i] * v[i]; }
    #pragma unroll
    for (int o = 16; o > 0; o >>= 1){
        s += __shfl_xor_sync(0xffffffffu, s, o);
        q += __shfl_xor_sync(0xffffffffu, q, o);
    }
    const float mean = s * (1.f / 1024.f);
    const float rstd = rsqrtf(q * (1.f / 1024.f) - mean * mean + 1e-5f);

    float* orow = out + row * FDIM;
    #pragma unroll
    for (int j = 0; j < 8; ++j){
        const int f4 = lane + j * 32;
        float4 g4 = ((const float4*)gamma)[f4];
        float4 b4 = ((const float4*)beta)[f4];
        float4 r;
        r.x = (v[j*4 + 0] - mean) * rstd * g4.x + b4.x;
        r.y = (v[j*4 + 1] - mean) * rstd * g4.y + b4.y;
        r.z = (v[j*4 + 2] - mean) * rstd * g4.z + b4.z;
        r.w = (v[j*4 + 3] - mean) * rstd * g4.w + b4.w;
        ((float4*)orow)[f4] = r;
    }
}

// ---------------------------------------------------------------------------
// Launch
// ---------------------------------------------------------------------------
extern "C" void kernel_launch(void* const* d_in, const int* in_sizes, int n_in,
                              void* d_out, int out_size)
{
    (void)in_sizes; (void)n_in; (void)out_size;
    const float* x     = (const float*)d_in[0];
    const float* Wq    = (const float*)d_in[1];
    const float* bq    = (const float*)d_in[2];
    const float* Wk    = (const float*)d_in[3];
    const float* bk    = (const float*)d_in[4];
    const float* Wv    = (const float*)d_in[5];
    const float* bv    = (const float*)d_in[6];
    const float* Wo    = (const float*)d_in[7];
    const float* bo    = (const float*)d_in[8];
    const float* gamma = (const float*)d_in[9];
    const float* beta  = (const float*)d_in[10];
    float* out = (float*)d_out;

    cudaFuncSetAttribute(gemm_hmma_kernel<0>, cudaFuncAttributeMaxDynamicSharedMemorySize, GEMM_DSMEM);
    cudaFuncSetAttribute(gemm_hmma_kernel<1>, cudaFuncAttributeMaxDynamicSharedMemorySize, GEMM_DSMEM);
    cudaFuncSetAttribute(attn_mma_kernel, cudaFuncAttributeMaxDynamicSharedMemorySize, ATTN_DSMEM);

    transw_kernel<<<dim3(32, 32, 4), dim3(32, 8)>>>(Wq, Wk, Wv, Wo, bq, bk, bv);
    gemm_hmma_kernel<0><<<dim3(NQKV / BN, TOKENS / BM), 256, GEMM_DSMEM>>>(x, nullptr);
    attn_mma_kernel<<<TOKENS / 8, 256, ATTN_DSMEM>>>();
    gemm_hmma_kernel<1><<<dim3(FDIM / BN, TOKENS / BM), 256, GEMM_DSMEM>>>(nullptr, bo);
    ln_kernel<<<TOKENS / 8, 256>>>(gamma, beta, out);
}